// round 2
// baseline (speedup 1.0000x reference)
#include <cuda_runtime.h>
#include <cuda_bf16.h>
#include <math.h>

// ---------------- problem constants ----------------
#define NFFT    1881
#define KPAD    1888            // NFFT padded to multiple of 16
#define STEPSZ  941
#define ZB      109
#define NFRAMES 468
#define NBATCH  8
#define MTOT    (NBATCH*NFRAMES)   // 3744 frames
#define NBINS   765                // bins 3..767
#define NPAD    1536               // 2*765 -> padded to 1536
#define TLEN    441000
#define NB941   941                // NFFT//2+1
#define LOG2_10 3.321928094887362f

// ---------------- scratch (static device memory; no allocations) ----------------
__device__ __align__(16) float g_XF[MTOT * KPAD];        // windowed frames  (28.3 MB)
__device__ __align__(16) float g_TW[KPAD * NPAD];        // scaled twiddles  (11.6 MB)
__device__ __align__(16) float g_CM[MTOT * NPAD];        // DFT re/im        (23.0 MB)
__device__ __align__(16) float g_BARK[NBINS * 112];      // bark overlap mat
__device__ __align__(16) float g_UEP[MTOT * 112];        // bark energies + noise
__device__ __align__(16) float g_SM[NBATCH * ZB * NFRAMES]; // smeared uep [b][z][t]
__device__ float g_W[KPAD];                              // framing hann (non-periodic)
__device__ float g_FC[ZB], g_SU0[ZB], g_WN[ZB], g_A[ZB], g_NORMI[ZB];
__device__ float g_FMAG[10 * NB941];
__device__ float g_FAC[1];

// ---------------- setup: window, band constants, Ec-based norm_inv ----------------
__global__ void k_consts() {
    int tid = threadIdx.x;
    for (int n = tid; n < KPAD; n += blockDim.x)
        g_W[n] = (n < NFFT) ? (float)(0.5 * (1.0 - cospi(2.0 * n / 1880.0))) : 0.f;
    if (tid < ZB) {
        double zL = 7.0 * asinh(80.0 / 650.0);
        double ze = zL + 0.25 * tid;
        double fcd = 650.0 * sinh((ze + 0.125) / 7.0);
        float fc = (float)fcd;
        g_FC[tid] = fc;
        g_SU0[tid] = -24.0f - 230.0f / fc;
        g_WN[tid] = (float)pow(10.0, 0.4 * 0.364 * pow(fcd / 1000.0, -0.8));
        double tau = 0.008 + 2.2 / fcd;
        g_A[tid] = (float)exp(-4.0 / (187.5 * tau));
    }
    __syncthreads();
    __shared__ float srow[ZB];
    if (tid < ZB) {                     // row sums of raw Ec
        int r = tid; float s = 0.f;
        for (int c = 0; c < ZB; c++) {
            float slope = (r <= c) ? 27.0f : g_SU0[r];
            float e = fminf(0.025f * (float)(r - c) * slope, 30.0f);
            s += exp2f(e * LOG2_10);
        }
        srow[r] = s;
    }
    __syncthreads();
    if (tid < ZB) {                     // norm_inv[r] = (sum_c (Ec[r,c]/srow[c])^0.4)^-2.5
        int r = tid; float t = 0.f;
        for (int c = 0; c < ZB; c++) {
            float slope = (r <= c) ? 27.0f : g_SU0[r];
            float e = fminf(0.025f * (float)(r - c) * slope, 30.0f);
            float ec = exp2f(e * LOG2_10) / srow[c];
            t += exp2f(0.4f * log2f(ec));
        }
        g_NORMI[r] = exp2f(-2.5f * log2f(t));
    }
}

// ---------------- setup: bark overlap matrix (fp64, faithful) ----------------
__global__ void k_barkmat() {
    int idx = blockIdx.x * blockDim.x + threadIdx.x;
    if (idx >= NBINS * ZB) return;
    int k = idx / ZB, j = idx % ZB;
    double df = 44100.0 / 1881.0;
    int bin = k + 3;
    double blo = bin * df - df / 2.0, bhi = bin * df + df / 2.0;
    double zL = 7.0 * asinh(80.0 / 650.0);
    double felo = 650.0 * sinh((zL + 0.25 * j) / 7.0);
    double fehi = 650.0 * sinh((zL + 0.25 * (j + 1)) / 7.0);
    double ov = fmin(bhi, fehi) - fmax(blo, felo);
    ov = fmax(ov, 0.0) / df;
    g_BARK[k * 112 + j] = (float)ov;
}

// ---------------- setup: FAC calibration (periodic hann + 1019.5 Hz sine) ----------------
__global__ void k_facmag() {
    int k = blockIdx.x;      // bin 0..940
    int fr = blockIdx.y;     // frame 0..9
    int tid = threadIdx.x;   // 128
    float re = 0.f, im = 0.f;
    for (int n = tid; n < NFFT; n += 128) {
        int t = fr * STEPSZ + n;
        int p = (t * 2039) % 88200;               // phase of sin(2*pi*1019.5*t/44100)
        float sv = sinpif((float)p * (1.0f / 44100.0f));
        float wp = 0.5f * (1.0f - cospif((float)(2 * n) * (1.0f / 1881.0f))); // periodic hann
        int m = (k * n) % NFFT;
        float sn, cs;
        sincospif((float)m * (2.0f / 1881.0f), &sn, &cs);
        float wx = wp * sv;
        re += wx * cs;
        im += wx * sn;
    }
    __shared__ float sre[128], sim[128];
    sre[tid] = re; sim[tid] = im; __syncthreads();
    for (int o = 64; o > 0; o >>= 1) {
        if (tid < o) { sre[tid] += sre[tid + o]; sim[tid] += sim[tid + o]; }
        __syncthreads();
    }
    if (tid == 0) g_FMAG[fr * NB941 + k] = sqrtf(sre[0] * sre[0] + sim[0] * sim[0]);
}

__global__ void k_facred() {
    __shared__ float sm[256];
    int tid = threadIdx.x;
    float total = 0.f;
    for (int fr = 0; fr < 10; fr++) {
        float mx = 0.f;
        for (int k = tid; k < NB941; k += 256) mx = fmaxf(mx, g_FMAG[fr * NB941 + k]);
        sm[tid] = mx; __syncthreads();
        for (int o = 128; o > 0; o >>= 1) {
            if (tid < o) sm[tid] = fmaxf(sm[tid], sm[tid + o]);
            __syncthreads();
        }
        if (tid == 0) total += sm[0];
        __syncthreads();
    }
    if (tid == 0) g_FAC[0] = exp2f(4.6f * LOG2_10) / (total * 0.1f);
}

// ---------------- setup: scaled twiddle matrix (FAC*EARW/NFFT folded in) ----------------
__global__ void k_tw() {
    int n = blockIdx.x;                // 0..KPAD-1
    float fac = g_FAC[0];
    for (int col = threadIdx.x; col < NPAD; col += blockDim.x) {
        float v = 0.f;
        int j = col >> 1;
        if (n < NFFT && j < NBINS) {
            int bin = j + 3;
            float f = 22050.0f * (float)bin / 941.0f;   // reference EARW freq grid
            float fk = f * 0.001f;
            float lgfk = log2f(fk);
            float Wdb = -2.184f * exp2f(-0.8f * lgfk)
                      + 6.5f * expf(-0.6f * (fk - 3.3f) * (fk - 3.3f))
                      - 0.001f * exp2f(3.6f * lgfk);
            float earw = exp2f(Wdb * (LOG2_10 / 20.f));
            float sc = fac * earw * (1.0f / 1881.0f);
            int m = (bin * n) % NFFT;
            float sn, cs;
            sincospif((float)m * (2.0f / 1881.0f), &sn, &cs);
            v = ((col & 1) ? sn : cs) * sc;
        }
        g_TW[n * NPAD + col] = v;
    }
}

// ---------------- window + frame ----------------
__global__ void k_window(const float* __restrict__ pred, const float* __restrict__ targ) {
    int fg = blockIdx.x;               // 0..3743
    int b = fg / NFRAMES, f = fg % NFRAMES;
    const float* src = (b < 4) ? pred + (size_t)b * TLEN : targ + (size_t)(b - 4) * TLEN;
    int start = f * STEPSZ;
    for (int n = threadIdx.x; n < KPAD; n += blockDim.x) {
        float v = 0.f;
        if (n < NFFT) {
            int s = start + n;
            float xv = (s < TLEN) ? src[s] : 0.f;
            v = xv * g_W[n];
        }
        g_XF[(size_t)fg * KPAD + n] = v;
    }
}

// ---------------- DFT as tiled fp32 GEMM: CM = XF @ TW ----------------
#define BM 128
#define BN 128
#define BK 16
__global__ __launch_bounds__(256, 2) void k_gemm() {
    __shared__ float As[BK][BM + 4];
    __shared__ float Bs[BK][BN];
    int bx = blockIdx.x, by = blockIdx.y;
    int tid = threadIdx.x;
    int tx = tid & 15, ty = tid >> 4;
    int row0 = by * BM, col0 = bx * BN;
    int am = tid >> 1;
    int ak = (tid & 1) * 8;
    int bk = tid >> 4;
    int bn = (tid & 15) * 8;
    float acc[8][8];
    #pragma unroll
    for (int i = 0; i < 8; i++)
        #pragma unroll
        for (int j = 0; j < 8; j++) acc[i][j] = 0.f;

    for (int kk = 0; kk < KPAD; kk += BK) {
        int gr = row0 + am;
        float4 a0 = {0,0,0,0}, a1 = {0,0,0,0};
        if (gr < MTOT) {
            const float4* p = (const float4*)&g_XF[(size_t)gr * KPAD + kk + ak];
            a0 = p[0]; a1 = p[1];
        }
        As[ak + 0][am] = a0.x; As[ak + 1][am] = a0.y; As[ak + 2][am] = a0.z; As[ak + 3][am] = a0.w;
        As[ak + 4][am] = a1.x; As[ak + 5][am] = a1.y; As[ak + 6][am] = a1.z; As[ak + 7][am] = a1.w;
        const float4* q = (const float4*)&g_TW[(size_t)(kk + bk) * NPAD + col0 + bn];
        *(float4*)&Bs[bk][bn]     = q[0];
        *(float4*)&Bs[bk][bn + 4] = q[1];
        __syncthreads();
        #pragma unroll
        for (int k = 0; k < BK; k++) {
            float4 ra0 = *(const float4*)&As[k][ty * 8];
            float4 ra1 = *(const float4*)&As[k][ty * 8 + 4];
            float4 rb0 = *(const float4*)&Bs[k][tx * 8];
            float4 rb1 = *(const float4*)&Bs[k][tx * 8 + 4];
            float ar[8] = {ra0.x, ra0.y, ra0.z, ra0.w, ra1.x, ra1.y, ra1.z, ra1.w};
            float br[8] = {rb0.x, rb0.y, rb0.z, rb0.w, rb1.x, rb1.y, rb1.z, rb1.w};
            #pragma unroll
            for (int i = 0; i < 8; i++)
                #pragma unroll
                for (int j = 0; j < 8; j++)
                    acc[i][j] = fmaf(ar[i], br[j], acc[i][j]);
        }
        __syncthreads();
    }
    #pragma unroll
    for (int i = 0; i < 8; i++) {
        int gr = row0 + ty * 8 + i;
        if (gr < MTOT) {
            float4 o0 = {acc[i][0], acc[i][1], acc[i][2], acc[i][3]};
            float4 o1 = {acc[i][4], acc[i][5], acc[i][6], acc[i][7]};
            *(float4*)&g_CM[(size_t)gr * NPAD + col0 + tx * 8]     = o0;
            *(float4*)&g_CM[(size_t)gr * NPAD + col0 + tx * 8 + 4] = o1;
        }
    }
}

// ---------------- |X|^2 -> bark energies (+ internal noise), 8 frames/block ----------------
__global__ void k_bark() {
    int fb = blockIdx.x;               // 0..467
    int tid = threadIdx.x;             // 128
    __shared__ float P[8][768];
    for (int i = 0; i < 8; i++) {
        int fg = fb * 8 + i;
        const float2* crow = (const float2*)&g_CM[(size_t)fg * NPAD];
        for (int j = tid; j < NBINS; j += 128) {
            float2 c = crow[j];
            P[i][j] = c.x * c.x + c.y * c.y;
        }
    }
    __syncthreads();
    if (tid < ZB) {
        float acc[8] = {0,0,0,0,0,0,0,0};
        for (int j = 0; j < NBINS; j++) {
            float bv = g_BARK[j * 112 + tid];
            #pragma unroll
            for (int i = 0; i < 8; i++) acc[i] += P[i][j] * bv;
        }
        float wn = g_WN[tid];
        for (int i = 0; i < 8; i++)
            g_UEP[(size_t)(fb * 8 + i) * 112 + tid] = fmaxf(acc[i], 1e-12f) + wn;
    }
}

// ---------------- frequency smearing (faithful to reference broadcasts) ----------------
__global__ void k_smear() {
    int fg = blockIdx.x;               // 0..3743
    int tid = threadIdx.x;             // 128
    __shared__ float m2[ZB], Su[ZB], icol[ZB];
    if (tid < ZB) {
        float lg = log2f(g_UEP[(size_t)fg * 112 + tid]);
        float L = 3.0102999566f * lg;                 // 10*log10
        m2[tid] = fminf(0.30102999566f * lg, 30.0f);  // min(L/10, 30)
        Su[tid] = g_SU0[tid] + 0.2f * L;
    }
    __syncthreads();
    if (tid < ZB) {
        int c = tid;
        float colsum = 0.f;
        for (int r = 0; r < ZB; r++) {
            float slope = (r <= c) ? 27.0f : Su[r];
            float e1 = 0.025f * (float)(r - c) * slope;
            float m = fminf(e1, 30.0f) + m2[r];
            colsum += exp2f(m * LOG2_10);
        }
        icol[c] = exp2f(-0.4f * log2f(colsum));       // colsum^-0.4
    }
    __syncthreads();
    if (tid < ZB) {
        int c = tid;
        float acc = 0.f;
        for (int r = 0; r < ZB; r++) {
            float slope = (r <= c) ? 27.0f : Su[r];
            float e1 = 0.025f * (float)(r - c) * slope;
            float m = fminf(e1, 30.0f) + m2[r];
            acc += exp2f(0.4f * LOG2_10 * m) * icol[r];
        }
        float E2 = exp2f(2.5f * log2f(acc)) * g_NORMI[c];
        int b = fg / NFRAMES, f = fg % NFRAMES;
        g_SM[((size_t)b * ZB + c) * NFRAMES + f] = E2;
    }
}

// ---------------- per-band IIR + max ----------------
__global__ void k_iir(float* __restrict__ out) {
    int idx = blockIdx.x * blockDim.x + threadIdx.x;   // (b*109+z)
    if (idx >= NBATCH * ZB) return;
    int z = idx % ZB;
    float a = g_A[z], b0 = 1.f - a;
    const float* row = &g_SM[(size_t)idx * NFRAMES];
    float* orow = &out[(size_t)idx * NFRAMES];
    float ef = 0.f;
    for (int t = 0; t < NFRAMES; t++) {
        float u = row[t];
        float xin = (t == 0) ? 0.f : u;
        ef = fmaf(a, ef, b0 * xin);
        orow[t] = fmaxf(ef, u);
    }
}

// ---------------- launch ----------------
extern "C" void kernel_launch(void* const* d_in, const int* in_sizes, int n_in,
                              void* d_out, int out_size) {
    const float* pred = (const float*)d_in[0];
    const float* targ = (const float*)d_in[1];
    float* out = (float*)d_out;

    k_consts<<<1, 128>>>();
    k_barkmat<<<(NBINS * ZB + 255) / 256, 256>>>();
    k_facmag<<<dim3(NB941, 10), 128>>>();
    k_facred<<<1, 256>>>();
    k_tw<<<KPAD, 256>>>();
    k_window<<<MTOT, 256>>>(pred, targ);
    k_gemm<<<dim3(NPAD / BN, (MTOT + BM - 1) / BM), 256>>>();
    k_bark<<<NFRAMES, 128>>>();
    k_smear<<<MTOT, 128>>>();
    k_iir<<<(NBATCH * ZB + 127) / 128, 128>>>(out);
}

// round 3
// speedup vs baseline: 1.0624x; 1.0624x over previous
#include <cuda_runtime.h>
#include <cuda_bf16.h>
#include <math.h>

// ---------------- problem constants ----------------
#define NFFT    1881
#define KPAD    1888            // NFFT padded to multiple of 16
#define STEPSZ  941
#define ZB      109
#define NFRAMES 468
#define NBATCH  8
#define MTOT    (NBATCH*NFRAMES)   // 3744 frames
#define NBINS   765                // bins 3..767
#define NPAD    1536               // 2*765 -> padded to 1536
#define TLEN    441000
#define LOG2_10 3.321928094887362f
#define KLO     20                 // calibration max search window
#define KHI     71
#define KWIN    (KHI-KLO)          // 51 bins

// ---------------- scratch (static device memory; no allocations) ----------------
__device__ __align__(16) float g_XF[MTOT * KPAD];        // windowed frames  (28.3 MB)
__device__ __align__(16) float g_TW[KPAD * NPAD];        // scaled twiddles  (11.6 MB)
__device__ __align__(16) float g_CM[MTOT * NPAD];        // DFT re/im        (23.0 MB)
__device__ __align__(16) float g_BARK[NBINS * 112];      // bark overlap mat
__device__ __align__(16) float g_UEP[MTOT * 112];        // bark energies + noise
__device__ __align__(16) float g_SM[NBATCH * ZB * NFRAMES]; // smeared uep [b][z][t]
__device__ __align__(16) float2 g_TRIG[NFFT];            // (cos,sin)(2*pi*m/1881), fp64-gen
__device__ __align__(16) float g_CALSW[10 * NFFT];       // calib: periodic-hann * sine
__device__ float g_ESC[NBINS];                           // earw/NFFT per column
__device__ float g_W[KPAD];                              // framing hann (non-periodic)
__device__ float g_FC[ZB], g_SU0[ZB], g_WN[ZB], g_A[ZB], g_NORMI[ZB];
__device__ float g_FMAG[10 * KWIN];
__device__ float g_FAC[1];

// ---------------- setup: window, tables, band constants, Ec-based norm_inv ----------------
__global__ void k_consts() {
    int tid = threadIdx.x;           // 256 threads
    for (int n = tid; n < KPAD; n += blockDim.x)
        g_W[n] = (n < NFFT) ? (float)(0.5 * (1.0 - cospi(2.0 * n / 1880.0))) : 0.f;
    // fp64 trig table for all DFT twiddles
    for (int m = tid; m < NFFT; m += blockDim.x) {
        double ph = 2.0 * (double)m / 1881.0;
        g_TRIG[m] = make_float2((float)cospi(ph), (float)sinpi(ph));
    }
    // calibration waveform: periodic hann * 1019.5 Hz sine, 10 frames
    for (int i = tid; i < 10 * NFFT; i += blockDim.x) {
        int fr = i / NFFT, n = i % NFFT;
        int t = fr * STEPSZ + n;
        int p = (t * 2039) % 88200;
        float sv = sinpif((float)p * (1.0f / 44100.0f));
        float wp = 0.5f * (1.0f - cospif((float)(2 * n) * (1.0f / 1881.0f)));
        g_CALSW[i] = wp * sv;
    }
    // per-column ear weighting scale (FAC applied later in k_tw)
    for (int j = tid; j < NBINS; j += blockDim.x) {
        int bin = j + 3;
        float f = 22050.0f * (float)bin / 941.0f;
        float fk = f * 0.001f;
        float lgfk = log2f(fk);
        float Wdb = -2.184f * exp2f(-0.8f * lgfk)
                  + 6.5f * expf(-0.6f * (fk - 3.3f) * (fk - 3.3f))
                  - 0.001f * exp2f(3.6f * lgfk);
        g_ESC[j] = exp2f(Wdb * (LOG2_10 / 20.f)) * (1.0f / 1881.0f);
    }
    if (tid < ZB) {
        double zL = 7.0 * asinh(80.0 / 650.0);
        double ze = zL + 0.25 * tid;
        double fcd = 650.0 * sinh((ze + 0.125) / 7.0);
        float fc = (float)fcd;
        g_FC[tid] = fc;
        g_SU0[tid] = -24.0f - 230.0f / fc;
        g_WN[tid] = (float)pow(10.0, 0.4 * 0.364 * pow(fcd / 1000.0, -0.8));
        double tau = 0.008 + 2.2 / fcd;
        g_A[tid] = (float)exp(-4.0 / (187.5 * tau));
    }
    __syncthreads();
    __shared__ float srow[ZB];
    if (tid < ZB) {                     // row sums of raw Ec
        int r = tid; float s = 0.f;
        for (int c = 0; c < ZB; c++) {
            float slope = (r <= c) ? 27.0f : g_SU0[r];
            float e = fminf(0.025f * (float)(r - c) * slope, 30.0f);
            s += exp2f(e * LOG2_10);
        }
        srow[r] = s;
    }
    __syncthreads();
    if (tid < ZB) {                     // norm_inv[r] = (sum_c (Ec[r,c]/srow[c])^0.4)^-2.5
        int r = tid; float t = 0.f;
        for (int c = 0; c < ZB; c++) {
            float slope = (r <= c) ? 27.0f : g_SU0[r];
            float e = fminf(0.025f * (float)(r - c) * slope, 30.0f);
            float ec = exp2f(e * LOG2_10) / srow[c];
            t += exp2f(0.4f * log2f(ec));
        }
        g_NORMI[r] = exp2f(-2.5f * log2f(t));
    }
}

// ---------------- setup: bark overlap matrix (fp64, faithful) ----------------
__global__ void k_barkmat() {
    int idx = blockIdx.x * blockDim.x + threadIdx.x;
    if (idx >= NBINS * ZB) return;
    int k = idx / ZB, j = idx % ZB;
    double df = 44100.0 / 1881.0;
    int bin = k + 3;
    double blo = bin * df - df / 2.0, bhi = bin * df + df / 2.0;
    double zL = 7.0 * asinh(80.0 / 650.0);
    double felo = 650.0 * sinh((zL + 0.25 * j) / 7.0);
    double fehi = 650.0 * sinh((zL + 0.25 * (j + 1)) / 7.0);
    double ov = fmin(bhi, fehi) - fmax(blo, felo);
    ov = fmax(ov, 0.0) / df;
    g_BARK[k * 112 + j] = (float)ov;
}

// ---------------- setup: FAC calibration magnitudes, bins KLO..KHI only ----------------
// (sine at 1019.5 Hz -> spectral peak at bin 43.5; the max cannot lie outside this window)
__global__ void k_facmag() {
    int k = blockIdx.x + KLO;   // bin
    int fr = blockIdx.y;        // frame 0..9
    int tid = threadIdx.x;      // 128
    const float* sw = &g_CALSW[fr * NFFT];
    float re = 0.f, im = 0.f;
    for (int n = tid; n < NFFT; n += 128) {
        int m = (k * n) % NFFT;
        float2 t = g_TRIG[m];
        float wx = sw[n];
        re += wx * t.x;
        im += wx * t.y;
    }
    __shared__ float sre[128], sim[128];
    sre[tid] = re; sim[tid] = im; __syncthreads();
    for (int o = 64; o > 0; o >>= 1) {
        if (tid < o) { sre[tid] += sre[tid + o]; sim[tid] += sim[tid + o]; }
        __syncthreads();
    }
    if (tid == 0) g_FMAG[fr * KWIN + blockIdx.x] = sqrtf(sre[0] * sre[0] + sim[0] * sim[0]);
}

__global__ void k_facred() {   // warp per frame
    int w = threadIdx.x >> 5, lane = threadIdx.x & 31;
    __shared__ float fmx[10];
    if (w < 10) {
        float mx = 0.f;
        for (int k = lane; k < KWIN; k += 32) mx = fmaxf(mx, g_FMAG[w * KWIN + k]);
        #pragma unroll
        for (int o = 16; o > 0; o >>= 1) mx = fmaxf(mx, __shfl_xor_sync(0xffffffff, mx, o));
        if (lane == 0) fmx[w] = mx;
    }
    __syncthreads();
    if (threadIdx.x == 0) {
        float total = 0.f;
        for (int fr = 0; fr < 10; fr++) total += fmx[fr];
        g_FAC[0] = exp2f(4.6f * LOG2_10) / (total * 0.1f);
    }
}

// ---------------- setup: scaled twiddle matrix via tables ----------------
__global__ void k_tw() {
    int n = blockIdx.x;                // 0..KPAD-1
    float fac = g_FAC[0];
    for (int col = threadIdx.x; col < NPAD; col += blockDim.x) {
        float v = 0.f;
        int j = col >> 1;
        if (n < NFFT && j < NBINS) {
            int m = ((j + 3) * n) % NFFT;
            float2 t = g_TRIG[m];
            v = ((col & 1) ? t.y : t.x) * (fac * g_ESC[j]);
        }
        g_TW[n * NPAD + col] = v;
    }
}

// ---------------- window + frame ----------------
__global__ void k_window(const float* __restrict__ pred, const float* __restrict__ targ) {
    int fg = blockIdx.x;               // 0..3743
    int b = fg / NFRAMES, f = fg % NFRAMES;
    const float* src = (b < 4) ? pred + (size_t)b * TLEN : targ + (size_t)(b - 4) * TLEN;
    int start = f * STEPSZ;
    for (int n = threadIdx.x; n < KPAD; n += blockDim.x) {
        float v = 0.f;
        if (n < NFFT) {
            int s = start + n;
            float xv = (s < TLEN) ? src[s] : 0.f;
            v = xv * g_W[n];
        }
        g_XF[(size_t)fg * KPAD + n] = v;
    }
}

// ---------------- DFT as double-buffered fp32 GEMM: CM = XF @ TW ----------------
#define BM 128
#define BN 128
#define BK 16
#define NT (KPAD / BK)
__global__ __launch_bounds__(256, 2) void k_gemm() {
    __shared__ float As[2][BK][BM + 4];
    __shared__ float Bs[2][BK][BN];
    const int tid = threadIdx.x;
    const int tx = tid & 15, ty = tid >> 4;
    const int row0 = blockIdx.y * BM, col0 = blockIdx.x * BN;
    const int am = tid >> 1, ak = (tid & 1) * 8;
    const int bk = tid >> 4, bn = (tid & 15) * 8;
    const int gr_a = row0 + am;
    const bool avalid = gr_a < MTOT;
    const float* Aptr = &g_XF[(size_t)(avalid ? gr_a : 0) * KPAD + ak];
    const float* Bptr = &g_TW[(size_t)bk * NPAD + col0 + bn];

    float4 a0 = {0,0,0,0}, a1 = {0,0,0,0}, b0, b1;
    if (avalid) { a0 = *(const float4*)Aptr; a1 = *(const float4*)(Aptr + 4); }
    b0 = *(const float4*)Bptr; b1 = *(const float4*)(Bptr + 4);
    As[0][ak + 0][am] = a0.x; As[0][ak + 1][am] = a0.y; As[0][ak + 2][am] = a0.z; As[0][ak + 3][am] = a0.w;
    As[0][ak + 4][am] = a1.x; As[0][ak + 5][am] = a1.y; As[0][ak + 6][am] = a1.z; As[0][ak + 7][am] = a1.w;
    *(float4*)&Bs[0][bk][bn]     = b0;
    *(float4*)&Bs[0][bk][bn + 4] = b1;
    __syncthreads();

    float acc[8][8];
    #pragma unroll
    for (int i = 0; i < 8; i++)
        #pragma unroll
        for (int j = 0; j < 8; j++) acc[i][j] = 0.f;

    for (int kt = 0; kt < NT; kt++) {
        const int cb = kt & 1, nb = cb ^ 1;
        const bool more = (kt + 1 < NT);
        if (more) {                      // issue next-tile gmem loads early
            const int kk = (kt + 1) * BK;
            a0 = make_float4(0,0,0,0); a1 = a0;
            if (avalid) { a0 = *(const float4*)(Aptr + kk); a1 = *(const float4*)(Aptr + kk + 4); }
            b0 = *(const float4*)(Bptr + (size_t)kk * NPAD);
            b1 = *(const float4*)(Bptr + (size_t)kk * NPAD + 4);
        }
        #pragma unroll
        for (int k = 0; k < BK; k++) {
            float4 ra0 = *(const float4*)&As[cb][k][ty * 8];
            float4 ra1 = *(const float4*)&As[cb][k][ty * 8 + 4];
            float4 rb0 = *(const float4*)&Bs[cb][k][tx * 8];
            float4 rb1 = *(const float4*)&Bs[cb][k][tx * 8 + 4];
            float ar[8] = {ra0.x, ra0.y, ra0.z, ra0.w, ra1.x, ra1.y, ra1.z, ra1.w};
            float br[8] = {rb0.x, rb0.y, rb0.z, rb0.w, rb1.x, rb1.y, rb1.z, rb1.w};
            #pragma unroll
            for (int i = 0; i < 8; i++)
                #pragma unroll
                for (int j = 0; j < 8; j++)
                    acc[i][j] = fmaf(ar[i], br[j], acc[i][j]);
        }
        if (more) {
            As[nb][ak + 0][am] = a0.x; As[nb][ak + 1][am] = a0.y; As[nb][ak + 2][am] = a0.z; As[nb][ak + 3][am] = a0.w;
            As[nb][ak + 4][am] = a1.x; As[nb][ak + 5][am] = a1.y; As[nb][ak + 6][am] = a1.z; As[nb][ak + 7][am] = a1.w;
            *(float4*)&Bs[nb][bk][bn]     = b0;
            *(float4*)&Bs[nb][bk][bn + 4] = b1;
        }
        __syncthreads();
    }
    #pragma unroll
    for (int i = 0; i < 8; i++) {
        int gr = row0 + ty * 8 + i;
        if (gr < MTOT) {
            float4 o0 = {acc[i][0], acc[i][1], acc[i][2], acc[i][3]};
            float4 o1 = {acc[i][4], acc[i][5], acc[i][6], acc[i][7]};
            *(float4*)&g_CM[(size_t)gr * NPAD + col0 + tx * 8]     = o0;
            *(float4*)&g_CM[(size_t)gr * NPAD + col0 + tx * 8 + 4] = o1;
        }
    }
}

// ---------------- |X|^2 -> bark energies (+ internal noise), 8 frames/block ----------------
__global__ void k_bark() {
    int fb = blockIdx.x;               // 0..467
    int tid = threadIdx.x;             // 128
    __shared__ float P[8][768];
    for (int i = 0; i < 8; i++) {
        int fg = fb * 8 + i;
        const float2* crow = (const float2*)&g_CM[(size_t)fg * NPAD];
        for (int j = tid; j < NBINS; j += 128) {
            float2 c = crow[j];
            P[i][j] = c.x * c.x + c.y * c.y;
        }
    }
    __syncthreads();
    if (tid < ZB) {
        float acc[8] = {0,0,0,0,0,0,0,0};
        for (int j = 0; j < NBINS; j++) {
            float bv = g_BARK[j * 112 + tid];
            #pragma unroll
            for (int i = 0; i < 8; i++) acc[i] += P[i][j] * bv;
        }
        float wn = g_WN[tid];
        for (int i = 0; i < 8; i++)
            g_UEP[(size_t)(fb * 8 + i) * 112 + tid] = fmaxf(acc[i], 1e-12f) + wn;
    }
}

// ---------------- frequency smearing (faithful to reference broadcasts) ----------------
__global__ void k_smear() {
    int fg = blockIdx.x;               // 0..3743
    int tid = threadIdx.x;             // 128
    __shared__ float m2[ZB], Su[ZB], icol[ZB];
    if (tid < ZB) {
        float lg = log2f(g_UEP[(size_t)fg * 112 + tid]);
        float L = 3.0102999566f * lg;                 // 10*log10
        m2[tid] = fminf(0.30102999566f * lg, 30.0f);  // min(L/10, 30)
        Su[tid] = g_SU0[tid] + 0.2f * L;
    }
    __syncthreads();
    if (tid < ZB) {
        int c = tid;
        float colsum = 0.f;
        for (int r = 0; r < ZB; r++) {
            float slope = (r <= c) ? 27.0f : Su[r];
            float e1 = 0.025f * (float)(r - c) * slope;
            float m = fminf(e1, 30.0f) + m2[r];
            colsum += exp2f(m * LOG2_10);
        }
        icol[c] = exp2f(-0.4f * log2f(colsum));       // colsum^-0.4
    }
    __syncthreads();
    if (tid < ZB) {
        int c = tid;
        float acc = 0.f;
        for (int r = 0; r < ZB; r++) {
            float slope = (r <= c) ? 27.0f : Su[r];
            float e1 = 0.025f * (float)(r - c) * slope;
            float m = fminf(e1, 30.0f) + m2[r];
            acc += exp2f(0.4f * LOG2_10 * m) * icol[r];
        }
        float E2 = exp2f(2.5f * log2f(acc)) * g_NORMI[c];
        int b = fg / NFRAMES, f = fg % NFRAMES;
        g_SM[((size_t)b * ZB + c) * NFRAMES + f] = E2;
    }
}

// ---------------- per-band IIR + max ----------------
__global__ void k_iir(float* __restrict__ out) {
    int idx = blockIdx.x * blockDim.x + threadIdx.x;   // (b*109+z)
    if (idx >= NBATCH * ZB) return;
    int z = idx % ZB;
    float a = g_A[z], b0 = 1.f - a;
    const float* row = &g_SM[(size_t)idx * NFRAMES];
    float* orow = &out[(size_t)idx * NFRAMES];
    float ef = 0.f;
    for (int t = 0; t < NFRAMES; t++) {
        float u = row[t];
        float xin = (t == 0) ? 0.f : u;
        ef = fmaf(a, ef, b0 * xin);
        orow[t] = fmaxf(ef, u);
    }
}

// ---------------- launch ----------------
extern "C" void kernel_launch(void* const* d_in, const int* in_sizes, int n_in,
                              void* d_out, int out_size) {
    const float* pred = (const float*)d_in[0];
    const float* targ = (const float*)d_in[1];
    float* out = (float*)d_out;

    k_consts<<<1, 256>>>();
    k_barkmat<<<(NBINS * ZB + 255) / 256, 256>>>();
    k_facmag<<<dim3(KWIN, 10), 128>>>();
    k_facred<<<1, 320>>>();
    k_tw<<<KPAD, 256>>>();
    k_window<<<MTOT, 256>>>(pred, targ);
    k_gemm<<<dim3(NPAD / BN, (MTOT + BM - 1) / BM), 256>>>();
    k_bark<<<NFRAMES, 128>>>();
    k_smear<<<MTOT, 128>>>();
    k_iir<<<(NBATCH * ZB + 127) / 128, 128>>>(out);
}

// round 6
// speedup vs baseline: 1.5294x; 1.4396x over previous
#include <cuda_runtime.h>
#include <cuda_bf16.h>
#include <mma.h>
#include <math.h>

// ---------------- problem constants ----------------
#define NFFT    1881
#define KPAD    1888
#define STEPSZ  941
#define ZB      109
#define NFRAMES 468
#define NBATCH  8
#define MTOT    (NBATCH*NFRAMES)
#define MPAD    3840
#define NBINS   765
#define NPAD    1536
#define TLEN    441000
#define LOG2_10 3.321928094887362f
#define KLO     20
#define KHI     71
#define KWIN    (KHI-KLO)
#define GK      16
#define NT      (KPAD/GK)
#define RS      24

// ---------------- scratch (static device memory; no allocations) ----------------
__device__ __align__(16) __nv_bfloat16 g_XFh[MTOT * KPAD];
__device__ __align__(16) __nv_bfloat16 g_XFl[MTOT * KPAD];
__device__ __align__(16) __nv_bfloat16 g_TWh[NPAD * KPAD];
__device__ __align__(16) __nv_bfloat16 g_TWl[NPAD * KPAD];
__device__ __align__(16) float g_CM[MPAD * NPAD];
__device__ __align__(16) float g_BARK[NBINS * 112];
__device__ __align__(16) float g_UEP[MTOT * 112];
__device__ __align__(16) float g_SM[NBATCH * ZB * NFRAMES];
__device__ __align__(16) float2 g_TRIG[NFFT];
__device__ __align__(16) float g_CALSW[10 * NFFT];
__device__ float g_ESC[NBINS];
__device__ float g_W[KPAD];
__device__ float g_FC[ZB], g_SU0[ZB], g_WN[ZB], g_A[ZB], g_NORMI[ZB];
__device__ float g_FMAG[10 * KWIN];
__device__ float g_FAC[1];

// ---------------- setup: window, tables, band constants, Ec-based norm_inv ----------------
__global__ void k_consts() {
    int tid = threadIdx.x;
    for (int n = tid; n < KPAD; n += blockDim.x)
        g_W[n] = (n < NFFT) ? (float)(0.5 * (1.0 - cospi(2.0 * n / 1880.0))) : 0.f;
    for (int m = tid; m < NFFT; m += blockDim.x) {
        double ph = 2.0 * (double)m / 1881.0;
        g_TRIG[m] = make_float2((float)cospi(ph), (float)sinpi(ph));
    }
    for (int i = tid; i < 10 * NFFT; i += blockDim.x) {
        int fr = i / NFFT, n = i % NFFT;
        int t = fr * STEPSZ + n;
        int p = (t * 2039) % 88200;
        float sv = sinpif((float)p * (1.0f / 44100.0f));
        float wp = 0.5f * (1.0f - cospif((float)(2 * n) * (1.0f / 1881.0f)));
        g_CALSW[i] = wp * sv;
    }
    for (int j = tid; j < NBINS; j += blockDim.x) {
        int bin = j + 3;
        float f = 22050.0f * (float)bin / 941.0f;
        float fk = f * 0.001f;
        float lgfk = log2f(fk);
        float Wdb = -2.184f * exp2f(-0.8f * lgfk)
                  + 6.5f * expf(-0.6f * (fk - 3.3f) * (fk - 3.3f))
                  - 0.001f * exp2f(3.6f * lgfk);
        g_ESC[j] = exp2f(Wdb * (LOG2_10 / 20.f)) * (1.0f / 1881.0f);
    }
    if (tid < ZB) {
        double zL = 7.0 * asinh(80.0 / 650.0);
        double ze = zL + 0.25 * tid;
        double fcd = 650.0 * sinh((ze + 0.125) / 7.0);
        float fc = (float)fcd;
        g_FC[tid] = fc;
        g_SU0[tid] = -24.0f - 230.0f / fc;
        g_WN[tid] = (float)pow(10.0, 0.4 * 0.364 * pow(fcd / 1000.0, -0.8));
        double tau = 0.008 + 2.2 / fcd;
        g_A[tid] = (float)exp(-4.0 / (187.5 * tau));
    }
    __syncthreads();
    __shared__ float srow[ZB];
    if (tid < ZB) {
        int r = tid; float s = 0.f;
        for (int c = 0; c < ZB; c++) {
            float slope = (r <= c) ? 27.0f : g_SU0[r];
            float e = fminf(0.025f * (float)(r - c) * slope, 30.0f);
            s += exp2f(e * LOG2_10);
        }
        srow[r] = s;
    }
    __syncthreads();
    if (tid < ZB) {
        int r = tid; float t = 0.f;
        for (int c = 0; c < ZB; c++) {
            float slope = (r <= c) ? 27.0f : g_SU0[r];
            float e = fminf(0.025f * (float)(r - c) * slope, 30.0f);
            float ec = exp2f(e * LOG2_10) / srow[c];
            t += exp2f(0.4f * log2f(ec));
        }
        g_NORMI[r] = exp2f(-2.5f * log2f(t));
    }
}

// ---------------- setup: bark overlap matrix (fp64, faithful) ----------------
__global__ void k_barkmat() {
    int idx = blockIdx.x * blockDim.x + threadIdx.x;
    if (idx >= NBINS * ZB) return;
    int k = idx / ZB, j = idx % ZB;
    double df = 44100.0 / 1881.0;
    int bin = k + 3;
    double blo = bin * df - df / 2.0, bhi = bin * df + df / 2.0;
    double zL = 7.0 * asinh(80.0 / 650.0);
    double felo = 650.0 * sinh((zL + 0.25 * j) / 7.0);
    double fehi = 650.0 * sinh((zL + 0.25 * (j + 1)) / 7.0);
    double ov = fmin(bhi, fehi) - fmax(blo, felo);
    ov = fmax(ov, 0.0) / df;
    g_BARK[k * 112 + j] = (float)ov;
}

// ---------------- setup: FAC calibration (peak near bin 43.5) ----------------
__global__ void k_facmag() {
    int k = blockIdx.x + KLO;
    int fr = blockIdx.y;
    int tid = threadIdx.x;
    const float* sw = &g_CALSW[fr * NFFT];
    float re = 0.f, im = 0.f;
    for (int n = tid; n < NFFT; n += 128) {
        int m = (k * n) % NFFT;
        float2 t = g_TRIG[m];
        float wx = sw[n];
        re += wx * t.x;
        im += wx * t.y;
    }
    __shared__ float sre[128], sim[128];
    sre[tid] = re; sim[tid] = im; __syncthreads();
    for (int o = 64; o > 0; o >>= 1) {
        if (tid < o) { sre[tid] += sre[tid + o]; sim[tid] += sim[tid + o]; }
        __syncthreads();
    }
    if (tid == 0) g_FMAG[fr * KWIN + blockIdx.x] = sqrtf(sre[0] * sre[0] + sim[0] * sim[0]);
}

__global__ void k_facred() {
    int w = threadIdx.x >> 5, lane = threadIdx.x & 31;
    __shared__ float fmx[10];
    if (w < 10) {
        float mx = 0.f;
        for (int k = lane; k < KWIN; k += 32) mx = fmaxf(mx, g_FMAG[w * KWIN + k]);
        for (int o = 16; o > 0; o >>= 1) mx = fmaxf(mx, __shfl_xor_sync(0xffffffff, mx, o));
        if (lane == 0) fmx[w] = mx;
    }
    __syncthreads();
    if (threadIdx.x == 0) {
        float total = 0.f;
        for (int fr = 0; fr < 10; fr++) total += fmx[fr];
        g_FAC[0] = exp2f(4.6f * LOG2_10) / (total * 0.1f);
    }
}

// ---------------- setup: transposed twiddle matrix, split bf16 hi/lo ----------------
__global__ void k_tw() {
    int col = blockIdx.x;
    float fac = g_FAC[0];
    int j = col >> 1;
    float sc = (j < NBINS) ? fac * g_ESC[j] : 0.f;
    int bin = j + 3;
    for (int n = threadIdx.x; n < KPAD; n += blockDim.x) {
        float v = 0.f;
        if (n < NFFT && j < NBINS) {
            int m = (bin * n) % NFFT;
            float2 t = g_TRIG[m];
            v = ((col & 1) ? t.y : t.x) * sc;
        }
        __nv_bfloat16 h = __float2bfloat16(v);
        float r = v - __bfloat162float(h);
        size_t o = (size_t)col * KPAD + n;
        g_TWh[o] = h;
        g_TWl[o] = __float2bfloat16(r);
    }
}

// ---------------- window + frame, split bf16 hi/lo ----------------
__global__ void k_window(const float* __restrict__ pred, const float* __restrict__ targ) {
    int fg = blockIdx.x;
    int b = fg / NFRAMES, f = fg % NFRAMES;
    const float* src = (b < 4) ? pred + (size_t)b * TLEN : targ + (size_t)(b - 4) * TLEN;
    int start = f * STEPSZ;
    for (int n = threadIdx.x; n < KPAD; n += blockDim.x) {
        float v = 0.f;
        if (n < NFFT) {
            int s = start + n;
            float xv = (s < TLEN) ? src[s] : 0.f;
            v = xv * g_W[n];
        }
        __nv_bfloat16 h = __float2bfloat16(v);
        float r = v - __bfloat162float(h);
        size_t o = (size_t)fg * KPAD + n;
        g_XFh[o] = h;
        g_XFl[o] = __float2bfloat16(r);
    }
}

// ---------------- split-bf16 tensor GEMM via wmma: CM = XF @ TW^T ----------------
// no inline asm, no function-like macros (toolchain-safe)
__global__ __launch_bounds__(256, 1) void k_gemm() {
    using namespace nvcuda;
    __shared__ __align__(16) __nv_bfloat16 sAh[128][RS];
    __shared__ __align__(16) __nv_bfloat16 sAl[128][RS];
    __shared__ __align__(16) __nv_bfloat16 sBh[128][RS];
    __shared__ __align__(16) __nv_bfloat16 sBl[128][RS];

    const int tid = threadIdx.x;
    const int w = tid >> 5;
    const int wm = w & 1;        // 2 warp-rows  -> 64 M each
    const int wn = w >> 1;       // 4 warp-cols  -> 32 N each
    const int row0 = blockIdx.y * 128, col0 = blockIdx.x * 128;

    const int lr = tid >> 1;            // loader row 0..127
    const int lh = (tid & 1) * 8;       // k-half 0/8
    const int gr = row0 + lr;
    const size_t aoff = (size_t)((gr < MTOT) ? gr : 0) * KPAD + lh;
    const size_t boff = (size_t)(col0 + lr) * KPAD + lh;

    wmma::fragment<wmma::accumulator, 16, 16, 16, float> acc[4][2];
    for (int i = 0; i < 4; i++) {
        for (int j = 0; j < 2; j++) wmma::fill_fragment(acc[i][j], 0.f);
    }

    uint4 rah = *(const uint4*)(g_XFh + aoff);
    uint4 ral = *(const uint4*)(g_XFl + aoff);
    uint4 rbh = *(const uint4*)(g_TWh + boff);
    uint4 rbl = *(const uint4*)(g_TWl + boff);

    for (int kt = 0; kt < NT; kt++) {
        __syncthreads();
        *(uint4*)(&sAh[lr][lh]) = rah;
        *(uint4*)(&sAl[lr][lh]) = ral;
        *(uint4*)(&sBh[lr][lh]) = rbh;
        *(uint4*)(&sBl[lr][lh]) = rbl;
        __syncthreads();
        if (kt + 1 < NT) {
            size_t kk = (size_t)(kt + 1) * GK;
            rah = *(const uint4*)(g_XFh + aoff + kk);
            ral = *(const uint4*)(g_XFl + aoff + kk);
            rbh = *(const uint4*)(g_TWh + boff + kk);
            rbl = *(const uint4*)(g_TWl + boff + kk);
        }

        wmma::fragment<wmma::matrix_b, 16, 16, 16, __nv_bfloat16, wmma::col_major> fbh[2], fbl[2];
        for (int ni = 0; ni < 2; ni++) {
            wmma::load_matrix_sync(fbh[ni], &sBh[wn * 32 + ni * 16][0], RS);
            wmma::load_matrix_sync(fbl[ni], &sBl[wn * 32 + ni * 16][0], RS);
        }
        for (int mi = 0; mi < 4; mi++) {
            wmma::fragment<wmma::matrix_a, 16, 16, 16, __nv_bfloat16, wmma::row_major> fah, fal;
            wmma::load_matrix_sync(fah, &sAh[wm * 64 + mi * 16][0], RS);
            wmma::load_matrix_sync(fal, &sAl[wm * 64 + mi * 16][0], RS);
            for (int ni = 0; ni < 2; ni++) {
                wmma::mma_sync(acc[mi][ni], fah, fbh[ni], acc[mi][ni]);
                wmma::mma_sync(acc[mi][ni], fah, fbl[ni], acc[mi][ni]);
                wmma::mma_sync(acc[mi][ni], fal, fbh[ni], acc[mi][ni]);
            }
        }
    }

    for (int mi = 0; mi < 4; mi++) {
        for (int ni = 0; ni < 2; ni++) {
            size_t r = (size_t)(row0 + wm * 64 + mi * 16);
            size_t c = (size_t)(col0 + wn * 32 + ni * 16);
            wmma::store_matrix_sync(&g_CM[r * NPAD + c], acc[mi][ni], NPAD, wmma::mem_row_major);
        }
    }
}

// ---------------- |X|^2 -> bark energies (+ internal noise), 8 frames/block ----------------
__global__ void k_bark() {
    int fb = blockIdx.x;
    int tid = threadIdx.x;
    __shared__ float P[8][768];
    for (int i = 0; i < 8; i++) {
        int fg = fb * 8 + i;
        const float2* crow = (const float2*)&g_CM[(size_t)fg * NPAD];
        for (int j = tid; j < NBINS; j += 128) {
            float2 c = crow[j];
            P[i][j] = c.x * c.x + c.y * c.y;
        }
    }
    __syncthreads();
    if (tid < ZB) {
        float acc[8] = {0, 0, 0, 0, 0, 0, 0, 0};
        for (int j = 0; j < NBINS; j++) {
            float bv = g_BARK[j * 112 + tid];
            for (int i = 0; i < 8; i++) acc[i] += P[i][j] * bv;
        }
        float wn = g_WN[tid];
        for (int i = 0; i < 8; i++)
            g_UEP[(size_t)(fb * 8 + i) * 112 + tid] = fmaxf(acc[i], 1e-12f) + wn;
    }
}

// ---------------- frequency smearing (faithful to reference broadcasts) ----------------
__global__ void k_smear() {
    int fg = blockIdx.x;
    int tid = threadIdx.x;
    __shared__ float m2[ZB], Su[ZB], icol[ZB];
    if (tid < ZB) {
        float lg = log2f(g_UEP[(size_t)fg * 112 + tid]);
        float L = 3.0102999566f * lg;
        m2[tid] = fminf(0.30102999566f * lg, 30.0f);
        Su[tid] = g_SU0[tid] + 0.2f * L;
    }
    __syncthreads();
    if (tid < ZB) {
        int c = tid;
        float colsum = 0.f;
        for (int r = 0; r < ZB; r++) {
            float slope = (r <= c) ? 27.0f : Su[r];
            float e1 = 0.025f * (float)(r - c) * slope;
            float m = fminf(e1, 30.0f) + m2[r];
            colsum += exp2f(m * LOG2_10);
        }
        icol[c] = exp2f(-0.4f * log2f(colsum));
    }
    __syncthreads();
    if (tid < ZB) {
        int c = tid;
        float acc = 0.f;
        for (int r = 0; r < ZB; r++) {
            float slope = (r <= c) ? 27.0f : Su[r];
            float e1 = 0.025f * (float)(r - c) * slope;
            float m = fminf(e1, 30.0f) + m2[r];
            acc += exp2f(0.4f * LOG2_10 * m) * icol[r];
        }
        float E2 = exp2f(2.5f * log2f(acc)) * g_NORMI[c];
        int b = fg / NFRAMES, f = fg % NFRAMES;
        g_SM[((size_t)b * ZB + c) * NFRAMES + f] = E2;
    }
}

// ---------------- per-band IIR + max ----------------
__global__ void k_iir(float* __restrict__ out) {
    int idx = blockIdx.x * blockDim.x + threadIdx.x;
    if (idx >= NBATCH * ZB) return;
    int z = idx % ZB;
    float a = g_A[z], b0 = 1.f - a;
    const float* row = &g_SM[(size_t)idx * NFRAMES];
    float* orow = &out[(size_t)idx * NFRAMES];
    float ef = 0.f;
    for (int t = 0; t < NFRAMES; t++) {
        float u = row[t];
        float xin = (t == 0) ? 0.f : u;
        ef = fmaf(a, ef, b0 * xin);
        orow[t] = fmaxf(ef, u);
    }
}

// ---------------- launch ----------------
extern "C" void kernel_launch(void* const* d_in, const int* in_sizes, int n_in,
                              void* d_out, int out_size) {
    const float* pred = (const float*)d_in[0];
    const float* targ = (const float*)d_in[1];
    float* out = (float*)d_out;

    k_consts<<<1, 256>>>();
    k_barkmat<<<(NBINS * ZB + 255) / 256, 256>>>();
    k_facmag<<<dim3(KWIN, 10), 128>>>();
    k_facred<<<1, 320>>>();
    k_tw<<<NPAD, 256>>>();
    k_window<<<MTOT, 256>>>(pred, targ);
    k_gemm<<<dim3(NPAD / 128, MPAD / 128), 256>>>();
    k_bark<<<NFRAMES, 128>>>();
    k_smear<<<MTOT, 128>>>();
    k_iir<<<(NBATCH * ZB + 127) / 128, 128>>>(out);
}